// round 11
// baseline (speedup 1.0000x reference)
#include <cuda_runtime.h>
#include <stdint.h>

#define NN 100000
#define NE 1200000
#define SCAN_B 1024
#define NBLK ((NN + SCAN_B - 1) / SCAN_B)   // 98

// ---------------- scratch (device globals: allocation-free) ----------------
__device__ __align__(128) float g_hA[NN * 64];    // h ping
__device__ __align__(128) float g_hB[NN * 64];    // h pong
__device__ __align__(128) float g_dinv[NN];
__device__ __align__(128) int   g_cnt[NN];        // in-degree (excl. self)
__device__ __align__(128) int   g_rowptr[NN + 1];
__device__ __align__(128) int   g_wpos[NN];
__device__ __align__(128) int   g_src[NE];        // CSR: sources grouped by dst
__device__ __align__(128) int   g_tmp[NN];
__device__ __align__(128) int   g_bsum[NBLK];

// ---------------- per-block int64 probe (ei L2-cached => free) -------------
__device__ __forceinline__ int probe_is64(const int* ei) {
    int az = 1;
#pragma unroll
    for (int j = 0; j < 32; j++) az &= (ei[2 * j + 1] == 0);
    return az;
}

// ---------------- masked-8 gather: uniform MLP=8, no serial tail -----------
template <int GRP>
__device__ __forceinline__ void gather8(const float4* __restrict__ h4,
                                        int beg, int end, int g, float4& acc) {
    for (int e = beg; e < end; e += 8) {
        int s[8];
#pragma unroll
        for (int u = 0; u < 8; u++) s[u] = g_src[min(e + u, end - 1)];
        float4 v[8];
#pragma unroll
        for (int u = 0; u < 8; u++) v[u] = h4[s[u] * GRP + g];
#pragma unroll
        for (int u = 0; u < 8; u++) {
            if (e + u < end) {
                acc.x += v[u].x; acc.y += v[u].y;
                acc.z += v[u].z; acc.w += v[u].w;
            }
        }
    }
}

// ---------------- count in-degrees, 4 edges/thread (g_cnt pre-zeroed) ------
__global__ void k_edges(const int* __restrict__ ei) {
    __shared__ int s_is64;
    if (threadIdx.x == 0) s_is64 = probe_is64(ei);
    __syncthreads();
    int stride = s_is64 ? 2 : 1;
    int e0 = (blockIdx.x * blockDim.x + threadIdx.x) * 4;
    int c[4];
#pragma unroll
    for (int u = 0; u < 4; u++) {
        int e = min(e0 + u, NE - 1);
        int cc = ei[(size_t)(NE + e) * stride];
        c[u] = min(max(cc, 0), NN - 1);
    }
#pragma unroll
    for (int u = 0; u < 4; u++)
        if (e0 + u < NE) atomicAdd(&g_cnt[c[u]], 1);
}

// ---------------- scan pass A: block-local inclusive scan ------------------
__global__ void k_scanA() {
    __shared__ int sm[SCAN_B];
    int i = blockIdx.x * SCAN_B + threadIdx.x;
    int v = (i < NN) ? g_cnt[i] : 0;
    sm[threadIdx.x] = v;
    __syncthreads();
    for (int off = 1; off < SCAN_B; off <<= 1) {
        int t = (threadIdx.x >= off) ? sm[threadIdx.x - off] : 0;
        __syncthreads();
        sm[threadIdx.x] += t;
        __syncthreads();
    }
    if (i < NN) g_tmp[i] = sm[threadIdx.x];
    if (threadIdx.x == SCAN_B - 1) g_bsum[blockIdx.x] = sm[threadIdx.x];
}

// ---------------- scan pass B: inline block-sum scan + finalize ------------
__global__ void k_scanC() {
    __shared__ int bs[128];
    if (threadIdx.x < 128)
        bs[threadIdx.x] = (threadIdx.x < NBLK) ? g_bsum[threadIdx.x] : 0;
    __syncthreads();
    for (int off = 1; off < 128; off <<= 1) {
        int t = (threadIdx.x >= off && threadIdx.x < 128) ? bs[threadIdx.x - off] : 0;
        __syncthreads();
        if (threadIdx.x < 128) bs[threadIdx.x] += t;
        __syncthreads();
    }
    int base = (blockIdx.x == 0) ? 0 : bs[blockIdx.x - 1];

    int i = blockIdx.x * SCAN_B + threadIdx.x;
    if (i < NN) {
        int inc = g_tmp[i] + base;
        g_rowptr[i + 1] = inc;
        g_wpos[i] = inc - g_cnt[i];
        g_dinv[i] = rsqrtf((float)(g_cnt[i] + 1));   // +1 self-loop
    }
    if (i == 0) g_rowptr[0] = 0;
}

// ---------------- fused: CSR fill (4 edges/thread) + layer-1 GEMM ----------
__global__ void k_fill_gemm1(const int* __restrict__ ei, int fill_blocks,
                             const float* __restrict__ x,
                             const float* __restrict__ W,
                             float* __restrict__ hout) {
    if (blockIdx.x < fill_blocks) {
        __shared__ int s_is64;
        if (threadIdx.x == 0) s_is64 = probe_is64(ei);
        __syncthreads();
        int stride = s_is64 ? 2 : 1;
        int e0 = (blockIdx.x * blockDim.x + threadIdx.x) * 4;
        int r[4], c[4];
#pragma unroll
        for (int u = 0; u < 4; u++) {
            int e = min(e0 + u, NE - 1);
            int rr = ei[(size_t)e * stride];
            int cc = ei[(size_t)(NE + e) * stride];
            r[u] = min(max(rr, 0), NN - 1);
            c[u] = min(max(cc, 0), NN - 1);
        }
        int p[4];
#pragma unroll
        for (int u = 0; u < 4; u++)
            p[u] = (e0 + u < NE) ? atomicAdd(&g_wpos[c[u]], 1) : 0;
#pragma unroll
        for (int u = 0; u < 4; u++)
            if (e0 + u < NE) g_src[p[u]] = r[u];
        return;
    }

    // ---- gemm1: DIN=64, DN=32, 32 nodes/block ----
    __shared__ float Ws[64 * 32];                 // 8KB
    __shared__ float xsh[32 * 68];                // 32 rows, XST=68 (16B-aligned)
    __shared__ float dsh[32];

    for (int i = threadIdx.x; i < 64 * 32; i += blockDim.x) Ws[i] = W[i];

    const int n0 = (blockIdx.x - fill_blocks) * 32;
    const float4* __restrict__ xg = reinterpret_cast<const float4*>(x);
    for (int i = threadIdx.x; i < 512; i += blockDim.x) {      // 32 rows * 16 f4
        int row = i >> 4, fi = i & 15;
        reinterpret_cast<float4*>(xsh + row * 68)[fi] = xg[(size_t)(n0 + row) * 16 + fi];
    }
    if (threadIdx.x < 32) dsh[threadIdx.x] = g_dinv[n0 + threadIdx.x];
    __syncthreads();

    const int l = threadIdx.x & 31;               // node (local)
    const int w = threadIdx.x >> 5;               // col-quad (0..7)
    const float* xr = xsh + l * 68;
    const float4* W4 = reinterpret_cast<const float4*>(Ws);

    float a0 = 0.f, a1 = 0.f, a2 = 0.f, a3 = 0.f;
#pragma unroll
    for (int k4 = 0; k4 < 16; k4++) {
        float4 xk = reinterpret_cast<const float4*>(xr)[k4];
#pragma unroll
        for (int kk = 0; kk < 4; kk++) {
            float xv = (&xk.x)[kk];
            float4 wv = W4[(k4 * 4 + kk) * 8 + w];
            a0 = fmaf(xv, wv.x, a0);
            a1 = fmaf(xv, wv.y, a1);
            a2 = fmaf(xv, wv.z, a2);
            a3 = fmaf(xv, wv.w, a3);
        }
    }
    float dn = dsh[l];
    float4 o; o.x = dn * a0; o.y = dn * a1; o.z = dn * a2; o.w = dn * a3;
    reinterpret_cast<float4*>(hout)[(size_t)(n0 + l) * 8 + w] = o;
}

// ---------------- layer-1 agg + layer-2 GEMM (HD=32 -> DN=64) --------------
__global__ void k_agg_gemm2(const float* __restrict__ hin,
                            float* __restrict__ hout,
                            const float* __restrict__ bprev,
                            const float* __restrict__ W) {
    __shared__ float Ws[32 * 64];                 // 8KB
    __shared__ float xsh[32 * 36];                // 32 z-rows, XST=36
    __shared__ float dsh[32];

    for (int i = threadIdx.x; i < 32 * 64; i += blockDim.x) Ws[i] = W[i];

    const int t = blockIdx.x * blockDim.x + threadIdx.x;
    const int n = t >> 3;
    const int g = t & 7;
    const int nw = threadIdx.x >> 3;

    const float4* __restrict__ h4 = reinterpret_cast<const float4*>(hin);

    float4 acc = h4[n * 8 + g];                   // self term
    gather8<8>(h4, g_rowptr[n], g_rowptr[n + 1], g, acc);

    const float dn = g_dinv[n];
    const float4 bp = reinterpret_cast<const float4*>(bprev)[g];
    float4 z;
    z.x = fmaxf(fmaf(dn, acc.x, bp.x), 0.0f);
    z.y = fmaxf(fmaf(dn, acc.y, bp.y), 0.0f);
    z.z = fmaxf(fmaf(dn, acc.z, bp.z), 0.0f);
    z.w = fmaxf(fmaf(dn, acc.w, bp.w), 0.0f);
    reinterpret_cast<float4*>(xsh + nw * 36)[g] = z;
    if (g == 0) dsh[nw] = dn;
    __syncthreads();

    // compute: node = lane, cols = warp*8 .. warp*8+7
    const int l = threadIdx.x & 31;
    const int w = threadIdx.x >> 5;
    const float* xr = xsh + l * 36;
    const float4* W4 = reinterpret_cast<const float4*>(Ws);

    float a[8];
#pragma unroll
    for (int j = 0; j < 8; j++) a[j] = 0.f;
#pragma unroll
    for (int k4 = 0; k4 < 8; k4++) {
        float4 xk = reinterpret_cast<const float4*>(xr)[k4];
#pragma unroll
        for (int kk = 0; kk < 4; kk++) {
            float xv = (&xk.x)[kk];
            int k = k4 * 4 + kk;
            float4 w0 = W4[k * 16 + w * 2];
            float4 w1 = W4[k * 16 + w * 2 + 1];
            a[0] = fmaf(xv, w0.x, a[0]); a[1] = fmaf(xv, w0.y, a[1]);
            a[2] = fmaf(xv, w0.z, a[2]); a[3] = fmaf(xv, w0.w, a[3]);
            a[4] = fmaf(xv, w1.x, a[4]); a[5] = fmaf(xv, w1.y, a[5]);
            a[6] = fmaf(xv, w1.z, a[6]); a[7] = fmaf(xv, w1.w, a[7]);
        }
    }
    const float dn2 = dsh[l];
    const int n2 = blockIdx.x * 32 + l;
    float4 o0, o1;
    o0.x = dn2 * a[0]; o0.y = dn2 * a[1]; o0.z = dn2 * a[2]; o0.w = dn2 * a[3];
    o1.x = dn2 * a[4]; o1.y = dn2 * a[5]; o1.z = dn2 * a[6]; o1.w = dn2 * a[7];
    reinterpret_cast<float4*>(hout)[(size_t)n2 * 16 + w * 2]     = o0;
    reinterpret_cast<float4*>(hout)[(size_t)n2 * 16 + w * 2 + 1] = o1;
}

// ---------------- layer-2 agg + layer-3 GEMM (HD=64 -> DN=64) --------------
__global__ void k_agg_gemm3(const float* __restrict__ hin,
                            float* __restrict__ hout,
                            const float* __restrict__ bprev,
                            const float* __restrict__ W) {
    __shared__ float Ws[64 * 64];                 // 16KB
    __shared__ float xsh[16 * 68];                // 16 z-rows, XST=68
    __shared__ float dsh[16];

    for (int i = threadIdx.x; i < 64 * 64; i += blockDim.x) Ws[i] = W[i];

    const int t = blockIdx.x * blockDim.x + threadIdx.x;
    const int n = t >> 4;
    const int g = t & 15;
    const int nw = threadIdx.x >> 4;

    const float4* __restrict__ h4 = reinterpret_cast<const float4*>(hin);

    float4 acc = h4[n * 16 + g];
    gather8<16>(h4, g_rowptr[n], g_rowptr[n + 1], g, acc);

    const float dn = g_dinv[n];
    const float4 bp = reinterpret_cast<const float4*>(bprev)[g];
    float4 z;
    z.x = fmaxf(fmaf(dn, acc.x, bp.x), 0.0f);
    z.y = fmaxf(fmaf(dn, acc.y, bp.y), 0.0f);
    z.z = fmaxf(fmaf(dn, acc.z, bp.z), 0.0f);
    z.w = fmaxf(fmaf(dn, acc.w, bp.w), 0.0f);
    reinterpret_cast<float4*>(xsh + nw * 68)[g] = z;
    if (g == 0) dsh[nw] = dn;
    __syncthreads();

    // compute: nl = lane&15, q = warp*2 + (lane>>4)
    const int l  = threadIdx.x & 31;
    const int w  = threadIdx.x >> 5;
    const int nl = l & 15;
    const int q  = w * 2 + (l >> 4);
    const float* xr = xsh + nl * 68;
    const float4* W4 = reinterpret_cast<const float4*>(Ws);

    float a0 = 0.f, a1 = 0.f, a2 = 0.f, a3 = 0.f;
#pragma unroll
    for (int k4 = 0; k4 < 16; k4++) {
        float4 xk = reinterpret_cast<const float4*>(xr)[k4];
#pragma unroll
        for (int kk = 0; kk < 4; kk++) {
            float xv = (&xk.x)[kk];
            float4 wv = W4[(k4 * 4 + kk) * 16 + q];
            a0 = fmaf(xv, wv.x, a0);
            a1 = fmaf(xv, wv.y, a1);
            a2 = fmaf(xv, wv.z, a2);
            a3 = fmaf(xv, wv.w, a3);
        }
    }
    const float dn2 = dsh[nl];
    const int n2 = blockIdx.x * 16 + nl;
    float4 o; o.x = dn2 * a0; o.y = dn2 * a1; o.z = dn2 * a2; o.w = dn2 * a3;
    reinterpret_cast<float4*>(hout)[(size_t)n2 * 16 + q] = o;
}

// ---------------- fused aggregate + bias + row L2-normalize ----------------
__global__ void k_agg_final(const float* __restrict__ hin,
                            const float* __restrict__ b3,
                            float* __restrict__ out) {
    const int t = blockIdx.x * blockDim.x + threadIdx.x;
    const int n = t >> 4;          // GRP = 16
    const int g = t & 15;

    const float4* __restrict__ h4 = reinterpret_cast<const float4*>(hin);

    float4 acc = h4[n * 16 + g];
    gather8<16>(h4, g_rowptr[n], g_rowptr[n + 1], g, acc);

    const float dn = g_dinv[n];
    const float4 bp = reinterpret_cast<const float4*>(b3)[g];
    float4 v;
    v.x = fmaf(dn, acc.x, bp.x);
    v.y = fmaf(dn, acc.y, bp.y);
    v.z = fmaf(dn, acc.z, bp.z);
    v.w = fmaf(dn, acc.w, bp.w);

    float s = v.x * v.x + v.y * v.y + v.z * v.z + v.w * v.w;
    s += __shfl_xor_sync(0xffffffffu, s, 1);
    s += __shfl_xor_sync(0xffffffffu, s, 2);
    s += __shfl_xor_sync(0xffffffffu, s, 4);
    s += __shfl_xor_sync(0xffffffffu, s, 8);
    float inv = 1.0f / fmaxf(sqrtf(s), 1e-12f);

    float4 o;
    o.x = v.x * inv; o.y = v.y * inv; o.z = v.z * inv; o.w = v.w * inv;
    reinterpret_cast<float4*>(out)[n * 16 + g] = o;
}

// ---------------- launch ----------------
extern "C" void kernel_launch(void* const* d_in, const int* in_sizes, int n_in,
                              void* d_out, int out_size) {
    const float* x  = (const float*)d_in[0];
    const int*   ei = (const int*)d_in[1];   // int32 (JAX x64 off) or int64 via probe
    const float* W1 = (const float*)d_in[2];
    const float* b1 = (const float*)d_in[3];
    const float* W2 = (const float*)d_in[4];
    const float* b2 = (const float*)d_in[5];
    const float* W3 = (const float*)d_in[6];
    const float* b3 = (const float*)d_in[7];
    float* out = (float*)d_out;

    float *hA, *hB;
    cudaGetSymbolAddress((void**)&hA, g_hA);
    cudaGetSymbolAddress((void**)&hB, g_hB);
    int* cnt;
    cudaGetSymbolAddress((void**)&cnt, g_cnt);

    const int TB = 256;
    const int EDGE4_BLKS = (NE / 4 + TB - 1) / TB;   // 1172 (4 edges/thread)
    const int G1_BLKS    = NN / 32;                  // 3125 (32 nodes/block)

    // CSR + dinv (shared by all 3 layers)
    cudaMemsetAsync(cnt, 0, NN * sizeof(int));
    k_edges<<<EDGE4_BLKS, TB>>>(ei);
    k_scanA<<<NBLK, SCAN_B>>>();
    k_scanC<<<NBLK, SCAN_B>>>();

    // CSR fill + Layer-1 GEMM (independent, one kernel)
    k_fill_gemm1<<<EDGE4_BLKS + G1_BLKS, TB>>>(ei, EDGE4_BLKS, x, W1, hA);

    // Layer 1 aggregate + Layer 2 GEMM: hB = dinv * (relu(agg(hA)+b1) @ W2)
    k_agg_gemm2<<<NN / 32, TB>>>(hA, hB, b1, W2);    // 3125 blocks
    // Layer 2 aggregate + Layer 3 GEMM: hA = dinv * (relu(agg(hB)+b2) @ W3)
    k_agg_gemm3<<<NN / 16, TB>>>(hB, hA, b2, W3);    // 6250 blocks
    // Layer 3 aggregate + b3 + row L2-normalize -> out
    k_agg_final<<<NN * 16 / TB, TB>>>(hA, b3, out);  // 6250 blocks
}